// round 11
// baseline (speedup 1.0000x reference)
#include <cuda_runtime.h>
#include <math.h>

#define B_DIM 128
#define N_DIM 1024
#define H_DIM 128
#define SK    128          // split-K factor for layer 1 (== grid size)
#define KC    (N_DIM / SK) // 8: K-chunk per CTA
#define GRID  128

// Scratch (allocation-free rule: device globals).
__device__ float g_c[B_DIM * N_DIM];                    // 512 KB correlation output
__device__ float g_part[SK * B_DIM * H_DIM];            // 8 MB layer-1 partials

// Device-wide barrier state (zero-initialized; correct across graph replays:
// count returns to 0 after each use, release epoch is monotonic).
__device__ unsigned int g_bar_count[2];
__device__ unsigned int g_bar_release[2];

__device__ __forceinline__ void grid_barrier(int idx) {
    __threadfence();            // publish this thread's global writes
    __syncthreads();            // all CTA threads' writes fenced before arrive
    if (threadIdx.x == 0) {
        volatile unsigned int* rel = g_bar_release;
        unsigned int epoch = rel[idx];
        unsigned int old = atomicAdd(&g_bar_count[idx], 1u);
        if (old == GRID - 1) {
            g_bar_count[idx] = 0;             // reset for next use/replay
            __threadfence();
            atomicAdd(&g_bar_release[idx], 1u);  // release
        } else {
            while (rel[idx] == epoch) { }
        }
        __threadfence();
    }
    __syncthreads();
}

__device__ __forceinline__ float celu1(float v) {
    return v > 0.f ? v : expm1f(v);
}

// Bank-conflict swizzle for FFT arrays.
#define SWZ(j) ((j) + ((j) >> 5))
#define FFT_LEN 1056

__device__ __forceinline__ float2 cmul(float2 a, float2 b) {
    return make_float2(a.x * b.x - a.y * b.y, a.x * b.y + a.y * b.x);
}
__device__ __forceinline__ float2 cadd(float2 a, float2 b) {
    return make_float2(a.x + b.x, a.y + b.y);
}
__device__ __forceinline__ float2 csub(float2 a, float2 b) {
    return make_float2(a.x - b.x, a.y - b.y);
}

// Radix-4 Stockham DIF stage (S = 1,4,16,64,256), one butterfly per local
// thread t in [0,256). No internal sync — caller barriers.
template <int S>
__device__ __forceinline__ void r4stage(const float2* __restrict__ in,
                                        float2* __restrict__ out,
                                        const float2* __restrict__ tw,
                                        int t) {
    const int q  = t & (S - 1);
    const int pS = t - q;

    float2 a0 = in[SWZ(t)];
    float2 a1 = in[SWZ(t + 256)];
    float2 a2 = in[SWZ(t + 512)];
    float2 a3 = in[SWZ(t + 768)];

    float2 w1 = tw[pS];
    float2 w2 = cmul(w1, w1);
    float2 w3 = cmul(w2, w1);

    float2 s02 = cadd(a0, a2), d02 = csub(a0, a2);
    float2 s13 = cadd(a1, a3), d13 = csub(a1, a3);

    float2 b0 = cadd(s02, s13);
    float2 b2 = csub(s02, s13);
    float2 mi = make_float2(d13.y, -d13.x);      // -i * d13
    float2 b1 = cadd(d02, mi);
    float2 b3 = csub(d02, mi);

    const int o = 4 * pS + q;
    out[SWZ(o)]         = b0;
    out[SWZ(o + S)]     = cmul(b1, w1);
    out[SWZ(o + 2 * S)] = cmul(b2, w2);
    out[SWZ(o + 3 * S)] = cmul(b3, w3);
}

// ============================================================================
// Fused kernel: corr (FFT) -> grid barrier -> l1 split-K GEMM -> grid barrier
// -> MLP tail. Grid 128 (1 CTA/SM, co-resident), 512 threads.
// ============================================================================
__global__ __launch_bounds__(512) void fused_kernel(
    const float* __restrict__ x,
    const float* __restrict__ W1, const float* __restrict__ b1,
    const float* __restrict__ W2, const float* __restrict__ b2,
    const float* __restrict__ W3, const float* __restrict__ b3,
    float* __restrict__ y)
{
    __shared__ __align__(16) char sraw[4 * FFT_LEN * sizeof(float2)
                                       + 256 * sizeof(float2)];

    const int bid = blockIdx.x;
    const int tid = threadIdx.x;

    // ---------------- Part A: circular autocorrelation via FFT --------------
    // c[b,p] = (1/N) IDFT( sum_d |DFT(x_d)|^2 )[p]; S real+even => IDFT == DFT
    {
        float2 (*buf)[FFT_LEN] = (float2(*)[FFT_LEN])sraw;
        float2* tw = (float2*)(sraw + 4 * FFT_LEN * sizeof(float2));

        const int t    = tid & 255;
        const int team = tid >> 8;
        const float* xb = x + (size_t)bid * N_DIM * 3;

        if (tid < 256) {
            float sv, cv;
            sincospif((float)tid * (1.0f / 512.0f), &sv, &cv);
            tw[tid] = make_float2(cv, -sv);
        }
        for (int q = tid; q < N_DIM; q += 512) {
            float v0 = xb[3 * q + 0];
            float v1 = xb[3 * q + 1];
            float v2 = xb[3 * q + 2];
            buf[0][SWZ(q)] = make_float2(v0, v1);   // team0: z = x0 + i*x1
            buf[2][SWZ(q)] = make_float2(v2, 0.f);  // team1: x2
        }
        __syncthreads();

        // Phase 1: both teams, 5 stages
        {
            float2* A = buf[2 * team];
            float2* B = buf[2 * team + 1];
            r4stage<1>(A, B, tw, t);    __syncthreads();
            r4stage<4>(B, A, tw, t);    __syncthreads();
            r4stage<16>(A, B, tw, t);   __syncthreads();
            r4stage<64>(B, A, tw, t);   __syncthreads();
            r4stage<256>(A, B, tw, t);  __syncthreads();
        }
        // Z in buf[1], X2 in buf[3]

        for (int k = tid; k < N_DIM; k += 512) {
            float2 a = buf[1][SWZ(k)];
            float2 c = buf[1][SWZ((N_DIM - k) & (N_DIM - 1))];
            float2 e = buf[3][SWZ(k)];
            float s = 0.5f * (a.x * a.x + a.y * a.y + c.x * c.x + c.y * c.y)
                    + (e.x * e.x + e.y * e.y);
            buf[0][SWZ(k)] = make_float2(s, 0.f);
        }
        __syncthreads();

        // Phase 2: FFT#3 on team0 only
        if (tid < 256) r4stage<1>(buf[0], buf[1], tw, t);    __syncthreads();
        if (tid < 256) r4stage<4>(buf[1], buf[0], tw, t);    __syncthreads();
        if (tid < 256) r4stage<16>(buf[0], buf[1], tw, t);   __syncthreads();
        if (tid < 256) r4stage<64>(buf[1], buf[0], tw, t);   __syncthreads();
        if (tid < 256) r4stage<256>(buf[0], buf[1], tw, t);  __syncthreads();

        const float inv = 1.0f / ((float)N_DIM * (float)N_DIM);
        float* cb = g_c + (size_t)bid * N_DIM;
        for (int p = tid; p < N_DIM; p += 512)
            cb[p] = buf[1][SWZ(p)].x * inv;
    }

    grid_barrier(0);   // all g_c visible everywhere

    // ---------------- Part B: layer 1 split-K GEMM ---------------------------
    // CTA bid handles K-chunk [bid*KC, bid*KC+KC); 512 threads, 4x8 tile each.
    {
        float (*ct)[B_DIM] = (float(*)[B_DIM])sraw;                    // [KC][128]
        float (*wt)[H_DIM] = (float(*)[H_DIM])(sraw + KC * B_DIM * 4); // [KC][128]

        const int k0 = bid * KC;

        {   // stage c^T chunk: each thread one float2
            int m = tid >> 2, h = tid & 3;
            float2 v = *(const float2*)&g_c[(size_t)m * N_DIM + k0 + 2 * h];
            ct[2 * h + 0][m] = v.x;
            ct[2 * h + 1][m] = v.y;
        }
        {   // stage W1 chunk
            int kk = tid >> 6, qq = tid & 63;
            float2 v = *(const float2*)&W1[(size_t)(k0 + kk) * H_DIM + 2 * qq];
            wt[kk][2 * qq + 0] = v.x;
            wt[kk][2 * qq + 1] = v.y;
        }
        __syncthreads();

        const int m0 = (tid >> 4) * 4;   // 4 batch rows
        const int n0 = (tid & 15) * 8;   // 8 output cols

        float4 acc[4][2];
#pragma unroll
        for (int i = 0; i < 4; i++) {
            acc[i][0] = make_float4(0.f, 0.f, 0.f, 0.f);
            acc[i][1] = make_float4(0.f, 0.f, 0.f, 0.f);
        }

#pragma unroll
        for (int kk = 0; kk < KC; kk++) {
            float4 aa = *(const float4*)&ct[kk][m0];
            float4 bb0 = *(const float4*)&wt[kk][n0];
            float4 bb1 = *(const float4*)&wt[kk][n0 + 4];
            float a[4] = {aa.x, aa.y, aa.z, aa.w};
#pragma unroll
            for (int i = 0; i < 4; i++) {
                acc[i][0].x = fmaf(a[i], bb0.x, acc[i][0].x);
                acc[i][0].y = fmaf(a[i], bb0.y, acc[i][0].y);
                acc[i][0].z = fmaf(a[i], bb0.z, acc[i][0].z);
                acc[i][0].w = fmaf(a[i], bb0.w, acc[i][0].w);
                acc[i][1].x = fmaf(a[i], bb1.x, acc[i][1].x);
                acc[i][1].y = fmaf(a[i], bb1.y, acc[i][1].y);
                acc[i][1].z = fmaf(a[i], bb1.z, acc[i][1].z);
                acc[i][1].w = fmaf(a[i], bb1.w, acc[i][1].w);
            }
        }

        float* dst = g_part + (size_t)bid * B_DIM * H_DIM;
#pragma unroll
        for (int i = 0; i < 4; i++) {
            *(float4*)&dst[(size_t)(m0 + i) * H_DIM + n0]     = acc[i][0];
            *(float4*)&dst[(size_t)(m0 + i) * H_DIM + n0 + 4] = acc[i][1];
        }
    }

    grid_barrier(1);   // all partials visible everywhere

    // ---------------- Part C: MLP tail for batch bid -------------------------
    {
        float* h1s  = (float*)sraw;                 // [128]
        float* red  = (float*)sraw + 128;           // [512]
        float* rsum = (float*)sraw + 128 + 512;     // [4]

        const int m = bid;
        const int j = tid & 127;
        const int quarter = tid >> 7;               // 0..3

        // phase 1: reduce 128 split-K partials, 32 per quarter
        float s = 0.f;
        {
            const float* base = g_part + (size_t)quarter * 32 * (B_DIM * H_DIM)
                                       + (size_t)m * H_DIM + j;
#pragma unroll 8
            for (int sk = 0; sk < 32; sk++)
                s += base[(size_t)sk * (B_DIM * H_DIM)];
        }
        red[tid] = s;
        __syncthreads();
        if (quarter == 0)
            h1s[j] = celu1(red[j] + red[j + 128] + red[j + 256] + red[j + 384]
                           + b1[j]);
        __syncthreads();

        // phase 2: layer 2 (128 -> 128), 4-way K-split
        float a = 0.f;
        {
            const float* w = W2 + (size_t)quarter * 32 * H_DIM + j;
            const float* h = h1s + quarter * 32;
#pragma unroll 8
            for (int k = 0; k < 32; k++)
                a = fmaf(h[k], w[(size_t)k * H_DIM], a);
        }
        __syncthreads();
        red[tid] = a;
        __syncthreads();

        // phase 3: celu, layer 3, reduce
        float v = 0.f;
        if (quarter == 0) {
            float h2 = celu1(red[j] + red[j + 128] + red[j + 256] + red[j + 384]
                             + b2[j]);
            v = h2 * W3[j];
#pragma unroll
            for (int off = 16; off; off >>= 1)
                v += __shfl_xor_sync(0xffffffffu, v, off);
            if ((j & 31) == 0) rsum[j >> 5] = v;
        }
        __syncthreads();
        if (tid == 0)
            y[m] = rsum[0] + rsum[1] + rsum[2] + rsum[3] + b3[0];
    }
}

extern "C" void kernel_launch(void* const* d_in, const int* in_sizes, int n_in,
                              void* d_out, int out_size) {
    const float* x  = (const float*)d_in[0];
    const float* W1 = (const float*)d_in[1];
    const float* b1 = (const float*)d_in[2];
    const float* W2 = (const float*)d_in[3];
    const float* b2 = (const float*)d_in[4];
    const float* W3 = (const float*)d_in[5];
    const float* b3 = (const float*)d_in[6];
    float* y = (float*)d_out;

    fused_kernel<<<GRID, 512>>>(x, W1, b1, W2, b2, W3, b3, y);
}